// round 1
// baseline (speedup 1.0000x reference)
#include <cuda_runtime.h>

// Problem constants
#define BB   16
#define CIN  8
#define COUT 32
#define HH   64
#define WW   64
#define K2   9
#define NC   8          // spline coefficients per feature
#define CE   (CIN * 9)  // 72 effective input channels: per cin {silu, 8 bases}
#define TILE 16
#define THREADS 256

#define FROWS 18        // TILE + 2 halo
#define FPIX  (FROWS * FROWS)          // 324
#define SF_FLOATS (CE * FPIX)          // 23328
#define SW_FLOATS (CE * K2 * COUT)     // 20736
#define SMEM_BYTES ((SF_FLOATS + SW_FLOATS) * 4)   // 176256

__device__ __forceinline__ float silu_f(float x) {
    return x / (1.0f + __expf(-x));
}

// De Boor-Cox recursion, degree 3, uniform knots t[j] = (j-3)*0.4 - 1.0 (j=0..11).
// Matches the reference recursion exactly (same formula, fp32).
__device__ __forceinline__ void bspline8(float x, float* __restrict__ out) {
    float t[12];
    #pragma unroll
    for (int j = 0; j < 12; ++j) t[j] = (float)(j - 3) * 0.4f - 1.0f;

    float b[11];
    #pragma unroll
    for (int j = 0; j < 11; ++j)
        b[j] = (x >= t[j] && x < t[j + 1]) ? 1.0f : 0.0f;

    #pragma unroll
    for (int k = 1; k <= 3; ++k) {
        #pragma unroll
        for (int j = 0; j < 10; ++j) {
            if (j < 11 - k) {
                b[j] = (x - t[j]) / (t[j + k] - t[j]) * b[j]
                     + (t[j + k + 1] - x) / (t[j + k + 1] - t[j + 1]) * b[j + 1];
            }
        }
    }
    #pragma unroll
    for (int s = 0; s < NC; ++s) out[s] = b[s];
}

__global__ void __launch_bounds__(THREADS, 1)
kan_conv_kernel(const float* __restrict__ x,
                const float* __restrict__ base_w,
                const float* __restrict__ spline_w,
                const float* __restrict__ spline_s,
                float* __restrict__ out)
{
    extern __shared__ float smem[];
    float* sF = smem;                 // [CE][18][18]
    float* sW = smem + SF_FLOATS;     // [CE][9][COUT]

    const int tid  = threadIdx.x;
    const int tile = blockIdx.x;      // 0..15
    const int b    = blockIdx.y;      // 0..15
    const int th0  = (tile >> 2) * TILE;
    const int tw0  = (tile & 3) * TILE;

    // ---- Phase 1: fused weights into smem: sW[ce][tap][oc] ----
    for (int i = tid; i < SW_FLOATS; i += THREADS) {
        const int oc  = i & (COUT - 1);
        const int tap = (i / COUT) % K2;
        const int ce  = i / (COUT * K2);
        const int c   = ce / 9;
        const int f   = ce % 9;
        const int widx = (oc * CIN + c) * K2 + tap;
        float w;
        if (f == 0) w = base_w[widx];
        else        w = spline_w[widx * NC + (f - 1)] * spline_s[widx];
        sW[i] = w;
    }

    // ---- Phase 2: feature tile with halo: sF[ce][r][cc] ----
    for (int i = tid; i < CIN * FPIX; i += THREADS) {
        const int cc = i % FROWS;
        const int r  = (i / FROWS) % FROWS;
        const int c  = i / FPIX;
        const int gh = th0 + r - 1;
        const int gw = tw0 + cc - 1;
        float v = 0.0f;
        if (gh >= 0 && gh < HH && gw >= 0 && gw < WW)
            v = x[((b * CIN + c) * HH + gh) * WW + gw];
        float bs[NC];
        bspline8(v, bs);
        const int base = (c * 9) * FPIX + r * FROWS + cc;
        sF[base] = silu_f(v);
        #pragma unroll
        for (int s = 0; s < NC; ++s)
            sF[base + (s + 1) * FPIX] = bs[s];
    }
    __syncthreads();

    // ---- Phase 3: 3x3 conv, 72 ce -> 32 oc, one pixel per thread ----
    const int r  = tid >> 4;   // 0..15
    const int cc = tid & 15;   // 0..15

    float acc[COUT];
    #pragma unroll
    for (int o = 0; o < COUT; ++o) acc[o] = 0.0f;

    #pragma unroll 2
    for (int ce = 0; ce < CE; ++ce) {
        float f9[9];
        #pragma unroll
        for (int dh = 0; dh < 3; ++dh)
            #pragma unroll
            for (int dw = 0; dw < 3; ++dw)
                f9[dh * 3 + dw] = sF[ce * FPIX + (r + dh) * FROWS + (cc + dw)];

        const float4* wv = reinterpret_cast<const float4*>(sW + ce * K2 * COUT);
        #pragma unroll
        for (int tap = 0; tap < 9; ++tap) {
            const float fv = f9[tap];
            #pragma unroll
            for (int o4 = 0; o4 < COUT / 4; ++o4) {
                const float4 w = wv[tap * (COUT / 4) + o4];
                acc[o4 * 4 + 0] += fv * w.x;
                acc[o4 * 4 + 1] += fv * w.y;
                acc[o4 * 4 + 2] += fv * w.z;
                acc[o4 * 4 + 3] += fv * w.w;
            }
        }
    }

    // ---- Write out: per-oc, warp-coalesced along w ----
    const int gh = th0 + r;
    const int gw = tw0 + cc;
    #pragma unroll
    for (int o = 0; o < COUT; ++o)
        out[((b * COUT + o) * HH + gh) * WW + gw] = acc[o];
}

extern "C" void kernel_launch(void* const* d_in, const int* in_sizes, int n_in,
                              void* d_out, int out_size) {
    const float* x   = (const float*)d_in[0];
    const float* bw  = (const float*)d_in[1];
    const float* sw  = (const float*)d_in[2];
    const float* ss  = (const float*)d_in[3];
    float* out       = (float*)d_out;

    cudaFuncSetAttribute(kan_conv_kernel,
                         cudaFuncAttributeMaxDynamicSharedMemorySize,
                         SMEM_BYTES);

    dim3 grid(16, BB);   // 16 spatial tiles x 16 batches
    kan_conv_kernel<<<grid, THREADS, SMEM_BYTES>>>(x, bw, sw, ss, out);
}

// round 2
// speedup vs baseline: 1.0113x; 1.0113x over previous
#include <cuda_runtime.h>

// Problem constants
#define BB   16
#define CIN  8
#define COUT 32
#define HH   64
#define WW   64
#define K2   9
#define NC   8          // spline coefficients per feature
#define CE   (CIN * 9)  // 72 effective input channels: per cin {silu, 8 bases}
#define TILE 16
#define THREADS 256

#define FROWS 18        // TILE + 2 halo
#define FPIX  (FROWS * FROWS)          // 324
#define SF_FLOATS (CE * FPIX)          // 23328
#define SW_FLOATS (CE * K2 * COUT)     // 20736
#define SMEM_BYTES ((SF_FLOATS + SW_FLOATS) * 4)   // 176256

__device__ __forceinline__ float silu_f(float x) {
    return x / (1.0f + __expf(-x));
}

// Packed f32x2 FMA: d = a*b + d on two packed fp32 lanes. Bit-identical to
// two scalar FFMA (round-to-nearest), 2 FMAs per issue slot on sm_103a.
__device__ __forceinline__ void ffma2(unsigned long long& d,
                                      unsigned long long a,
                                      unsigned long long b) {
    asm("fma.rn.f32x2 %0, %1, %2, %0;" : "+l"(d) : "l"(a), "l"(b));
}

__device__ __forceinline__ unsigned long long pack2(float v) {
    unsigned long long p;
    asm("mov.b64 %0, {%1, %1};" : "=l"(p) : "f"(v));
    return p;
}

__device__ __forceinline__ void unpack2(unsigned long long p, float& lo, float& hi) {
    asm("mov.b64 {%0, %1}, %2;" : "=f"(lo), "=f"(hi) : "l"(p));
}

// De Boor-Cox recursion, degree 3, uniform knots t[j] = (j-3)*0.4 - 1.0.
// Matches the reference recursion exactly (same formula, fp32).
__device__ __forceinline__ void bspline8(float x, float* __restrict__ out) {
    float t[12];
    #pragma unroll
    for (int j = 0; j < 12; ++j) t[j] = (float)(j - 3) * 0.4f - 1.0f;

    float b[11];
    #pragma unroll
    for (int j = 0; j < 11; ++j)
        b[j] = (x >= t[j] && x < t[j + 1]) ? 1.0f : 0.0f;

    #pragma unroll
    for (int k = 1; k <= 3; ++k) {
        #pragma unroll
        for (int j = 0; j < 10; ++j) {
            if (j < 11 - k) {
                b[j] = (x - t[j]) / (t[j + k] - t[j]) * b[j]
                     + (t[j + k + 1] - x) / (t[j + k + 1] - t[j + 1]) * b[j + 1];
            }
        }
    }
    #pragma unroll
    for (int s = 0; s < NC; ++s) out[s] = b[s];
}

__global__ void __launch_bounds__(THREADS, 1)
kan_conv_kernel(const float* __restrict__ x,
                const float* __restrict__ base_w,
                const float* __restrict__ spline_w,
                const float* __restrict__ spline_s,
                float* __restrict__ out)
{
    extern __shared__ float smem[];
    float* sF = smem;                 // [CE][18][18]
    float* sW = smem + SF_FLOATS;     // [CE][9][COUT]

    const int tid  = threadIdx.x;
    const int tile = blockIdx.x;      // 0..15
    const int b    = blockIdx.y;      // 0..15
    const int th0  = (tile >> 2) * TILE;
    const int tw0  = (tile & 3) * TILE;

    // ---- Phase 1: fused weights into smem: sW[ce][tap][oc] ----
    for (int i = tid; i < SW_FLOATS; i += THREADS) {
        const int oc  = i & (COUT - 1);
        const int tap = (i / COUT) % K2;
        const int ce  = i / (COUT * K2);
        const int c   = ce / 9;
        const int f   = ce % 9;
        const int widx = (oc * CIN + c) * K2 + tap;
        float w;
        if (f == 0) w = base_w[widx];
        else        w = spline_w[widx * NC + (f - 1)] * spline_s[widx];
        sW[i] = w;
    }

    // ---- Phase 2: feature tile with halo: sF[ce][r][cc] ----
    for (int i = tid; i < CIN * FPIX; i += THREADS) {
        const int cc = i % FROWS;
        const int r  = (i / FROWS) % FROWS;
        const int c  = i / FPIX;
        const int gh = th0 + r - 1;
        const int gw = tw0 + cc - 1;
        float v = 0.0f;
        if (gh >= 0 && gh < HH && gw >= 0 && gw < WW)
            v = x[((b * CIN + c) * HH + gh) * WW + gw];
        float bs[NC];
        bspline8(v, bs);
        const int base = (c * 9) * FPIX + r * FROWS + cc;
        sF[base] = silu_f(v);
        #pragma unroll
        for (int s = 0; s < NC; ++s)
            sF[base + (s + 1) * FPIX] = bs[s];
    }
    __syncthreads();

    // ---- Phase 3: 3x3 conv, 72 ce -> 32 oc, one pixel per thread.
    //      Accumulators: 16 packed f32x2 (oc pairs {2j, 2j+1}).
    const int r  = tid >> 4;   // 0..15
    const int cc = tid & 15;   // 0..15

    unsigned long long acc[COUT / 2];
    #pragma unroll
    for (int o = 0; o < COUT / 2; ++o) acc[o] = 0ULL;

    #pragma unroll 2
    for (int ce = 0; ce < CE; ++ce) {
        float f9[9];
        #pragma unroll
        for (int dh = 0; dh < 3; ++dh)
            #pragma unroll
            for (int dw = 0; dw < 3; ++dw)
                f9[dh * 3 + dw] = sF[ce * FPIX + (r + dh) * FROWS + (cc + dw)];

        // Weights for this ce as packed pairs: one LDS.128 = 2 FFMA2 operands.
        const ulonglong2* wv =
            reinterpret_cast<const ulonglong2*>(sW + ce * K2 * COUT);

        #pragma unroll
        for (int tap = 0; tap < 9; ++tap) {
            const unsigned long long fp = pack2(f9[tap]);
            #pragma unroll
            for (int q = 0; q < COUT / 4; ++q) {   // 8 ulonglong2 per tap
                const ulonglong2 w = wv[tap * (COUT / 4) + q];
                ffma2(acc[q * 2 + 0], fp, w.x);
                ffma2(acc[q * 2 + 1], fp, w.y);
            }
        }
    }

    // ---- Write out: per-oc planes, warp-coalesced along w ----
    const int gh = th0 + r;
    const int gw = tw0 + cc;
    #pragma unroll
    for (int j = 0; j < COUT / 2; ++j) {
        float lo, hi;
        unpack2(acc[j], lo, hi);
        out[((b * COUT + (2 * j + 0)) * HH + gh) * WW + gw] = lo;
        out[((b * COUT + (2 * j + 1)) * HH + gh) * WW + gw] = hi;
    }
}

extern "C" void kernel_launch(void* const* d_in, const int* in_sizes, int n_in,
                              void* d_out, int out_size) {
    const float* x   = (const float*)d_in[0];
    const float* bw  = (const float*)d_in[1];
    const float* sw  = (const float*)d_in[2];
    const float* ss  = (const float*)d_in[3];
    float* out       = (float*)d_out;

    cudaFuncSetAttribute(kan_conv_kernel,
                         cudaFuncAttributeMaxDynamicSharedMemorySize,
                         SMEM_BYTES);

    dim3 grid(16, BB);   // 16 spatial tiles x 16 batches
    kan_conv_kernel<<<grid, THREADS, SMEM_BYTES>>>(x, bw, sw, ss, out);
}

// round 3
// speedup vs baseline: 1.1293x; 1.1166x over previous
#include <cuda_runtime.h>

// Problem constants
#define BB   16
#define CIN  8
#define COUT 32
#define HH   64
#define WW   64
#define K2   9
#define NC   8          // spline coefficients per feature
#define NF   9          // features per cin: silu + 8 spline bases
#define CE   (CIN * NF) // 72 effective input channels
#define TILE 16
#define THREADS 256

#define FROWS 18                       // TILE + 2 halo
#define FPIX  (FROWS * FROWS)          // 324
#define SF_FLOATS (NF * FPIX)          // 2916  (one cin's 9 feature planes)
#define SW_FLOATS (CE * K2 * COUT)     // 20736
#define SMEM_BYTES ((SF_FLOATS + SW_FLOATS) * 4)   // 94608

__device__ __forceinline__ float silu_f(float x) {
    return x / (1.0f + __expf(-x));
}

// Packed f32x2 FMA: d = a*b + d on two packed fp32 lanes. Bit-identical to
// two scalar FFMA (round-to-nearest), one issue slot on sm_103a.
__device__ __forceinline__ void ffma2(unsigned long long& d,
                                      unsigned long long a,
                                      unsigned long long b) {
    asm("fma.rn.f32x2 %0, %1, %2, %0;" : "+l"(d) : "l"(a), "l"(b));
}

__device__ __forceinline__ unsigned long long pack2(float v) {
    unsigned long long p;
    asm("mov.b64 %0, {%1, %1};" : "=l"(p) : "f"(v));
    return p;
}

__device__ __forceinline__ void unpack2(unsigned long long p, float& lo, float& hi) {
    asm("mov.b64 {%0, %1}, %2;" : "=f"(lo), "=f"(hi) : "l"(p));
}

// De Boor-Cox recursion, degree 3, uniform knots t[j] = (j-3)*0.4 - 1.0.
// Matches the reference recursion exactly (same formula, fp32).
__device__ __forceinline__ void bspline8(float x, float* __restrict__ out) {
    float t[12];
    #pragma unroll
    for (int j = 0; j < 12; ++j) t[j] = (float)(j - 3) * 0.4f - 1.0f;

    float b[11];
    #pragma unroll
    for (int j = 0; j < 11; ++j)
        b[j] = (x >= t[j] && x < t[j + 1]) ? 1.0f : 0.0f;

    #pragma unroll
    for (int k = 1; k <= 3; ++k) {
        #pragma unroll
        for (int j = 0; j < 10; ++j) {
            if (j < 11 - k) {
                b[j] = (x - t[j]) / (t[j + k] - t[j]) * b[j]
                     + (t[j + k + 1] - x) / (t[j + k + 1] - t[j + 1]) * b[j + 1];
            }
        }
    }
    #pragma unroll
    for (int s = 0; s < NC; ++s) out[s] = b[s];
}

__global__ void __launch_bounds__(THREADS, 2)
kan_conv_kernel(const float* __restrict__ x,
                const float* __restrict__ base_w,
                const float* __restrict__ spline_w,
                const float* __restrict__ spline_s,
                float* __restrict__ out)
{
    extern __shared__ float smem[];
    float* sF = smem;                 // [NF][18][18]  (current cin only)
    float* sW = smem + SF_FLOATS;     // [CE][9][COUT]

    const int tid  = threadIdx.x;
    const int tile = blockIdx.x;      // 0..15
    const int b    = blockIdx.y;      // 0..15
    const int th0  = (tile >> 2) * TILE;
    const int tw0  = (tile & 3) * TILE;

    // ---- Phase 1: fused weights into smem: sW[ce][tap][oc] ----
    for (int i = tid; i < SW_FLOATS; i += THREADS) {
        const int oc  = i & (COUT - 1);
        const int tap = (i / COUT) % K2;
        const int ce  = i / (COUT * K2);
        const int c   = ce / NF;
        const int f   = ce % NF;
        const int widx = (oc * CIN + c) * K2 + tap;
        float w;
        if (f == 0) w = base_w[widx];
        else        w = spline_w[widx * NC + (f - 1)] * spline_s[widx];
        sW[i] = w;
    }

    // Per-thread pixel coords for the conv phase.
    const int r  = tid >> 4;   // 0..15
    const int cc = tid & 15;   // 0..15

    unsigned long long acc[COUT / 2];
    #pragma unroll
    for (int o = 0; o < COUT / 2; ++o) acc[o] = 0ULL;

    // ---- Streamed over input channels: features for one cin at a time ----
    for (int c = 0; c < CIN; ++c) {
        __syncthreads();   // previous conv done consuming sF (and 1st iter: sW ready)

        // Phase 2: feature planes for this cin: sF[f][r][cc], 324 px
        for (int i = tid; i < FPIX; i += THREADS) {
            const int pc = i % FROWS;
            const int pr = i / FROWS;
            const int gh = th0 + pr - 1;
            const int gw = tw0 + pc - 1;
            float v = 0.0f;
            if (gh >= 0 && gh < HH && gw >= 0 && gw < WW)
                v = x[((b * CIN + c) * HH + gh) * WW + gw];
            float bs[NC];
            bspline8(v, bs);
            sF[i] = silu_f(v);
            #pragma unroll
            for (int s = 0; s < NC; ++s)
                sF[(s + 1) * FPIX + i] = bs[s];
        }
        __syncthreads();

        // Phase 3: conv-accumulate the 9 feature planes of this cin.
        #pragma unroll
        for (int f = 0; f < NF; ++f) {
            float f9[9];
            #pragma unroll
            for (int dh = 0; dh < 3; ++dh)
                #pragma unroll
                for (int dw = 0; dw < 3; ++dw)
                    f9[dh * 3 + dw] = sF[f * FPIX + (r + dh) * FROWS + (cc + dw)];

            const int ce = c * NF + f;
            const ulonglong2* wv =
                reinterpret_cast<const ulonglong2*>(sW + ce * K2 * COUT);

            #pragma unroll
            for (int tap = 0; tap < 9; ++tap) {
                const unsigned long long fp = pack2(f9[tap]);
                #pragma unroll
                for (int q = 0; q < COUT / 4; ++q) {   // 8 ulonglong2 per tap
                    const ulonglong2 w = wv[tap * (COUT / 4) + q];
                    ffma2(acc[q * 2 + 0], fp, w.x);
                    ffma2(acc[q * 2 + 1], fp, w.y);
                }
            }
        }
    }

    // ---- Write out: per-oc planes, warp-coalesced along w ----
    const int gh = th0 + r;
    const int gw = tw0 + cc;
    #pragma unroll
    for (int j = 0; j < COUT / 2; ++j) {
        float lo, hi;
        unpack2(acc[j], lo, hi);
        out[((b * COUT + (2 * j + 0)) * HH + gh) * WW + gw] = lo;
        out[((b * COUT + (2 * j + 1)) * HH + gh) * WW + gw] = hi;
    }
}

extern "C" void kernel_launch(void* const* d_in, const int* in_sizes, int n_in,
                              void* d_out, int out_size) {
    const float* x   = (const float*)d_in[0];
    const float* bw  = (const float*)d_in[1];
    const float* sw  = (const float*)d_in[2];
    const float* ss  = (const float*)d_in[3];
    float* out       = (float*)d_out;

    cudaFuncSetAttribute(kan_conv_kernel,
                         cudaFuncAttributeMaxDynamicSharedMemorySize,
                         SMEM_BYTES);

    dim3 grid(16, BB);   // 16 spatial tiles x 16 batches
    kan_conv_kernel<<<grid, THREADS, SMEM_BYTES>>>(x, bw, sw, ss, out);
}

// round 4
// speedup vs baseline: 1.7304x; 1.5323x over previous
#include <cuda_runtime.h>

// Problem constants
#define BB   16
#define CIN  8
#define COUT 32
#define HH   64
#define WW   64
#define K2   9
#define NC   8          // spline coefficients per feature
#define NF   9          // features per cin: silu + 8 spline bases
#define CE   (CIN * NF) // 72 effective input channels
#define TILE 16
#define THREADS 256

#define FROWS 18                       // TILE + 2 halo
#define FPIX  (FROWS * FROWS)          // 324
#define SF_FLOATS (NF * FPIX)          // 2916  (one cin's 9 feature planes)
#define WCHUNK   (NF * K2 * COUT)      // 2592  (one cin's fused weights)
#define SMEM_BYTES ((SF_FLOATS + WCHUNK) * 4)   // 22032

// Fused weights, computed once per launch by kan_fuse_kernel.
// Layout: gw[c][f][tap][oc], c=cin, f=feature(0=silu,1..8=spline), oc fastest.
__device__ float g_fused[CIN * NF * K2 * COUT];

__device__ __forceinline__ float silu_f(float x) {
    return x / (1.0f + __expf(-x));
}

// Packed f32x2 FMA: d = a*b + d on two packed fp32 lanes. Bit-identical to
// two scalar FFMA (round-to-nearest), one issue slot on sm_103a.
__device__ __forceinline__ void ffma2(unsigned long long& d,
                                      unsigned long long a,
                                      unsigned long long b) {
    asm("fma.rn.f32x2 %0, %1, %2, %0;" : "+l"(d) : "l"(a), "l"(b));
}

__device__ __forceinline__ unsigned long long pack2(float v) {
    unsigned long long p;
    asm("mov.b64 %0, {%1, %1};" : "=l"(p) : "f"(v));
    return p;
}

__device__ __forceinline__ void unpack2(unsigned long long p, float& lo, float& hi) {
    asm("mov.b64 {%0, %1}, %2;" : "=f"(lo), "=f"(hi) : "l"(p));
}

// De Boor-Cox recursion, degree 3, uniform knots t[j] = (j-3)*0.4 - 1.0.
// Matches the reference recursion exactly (same formula, fp32).
__device__ __forceinline__ void bspline8(float x, float* __restrict__ out) {
    float t[12];
    #pragma unroll
    for (int j = 0; j < 12; ++j) t[j] = (float)(j - 3) * 0.4f - 1.0f;

    float b[11];
    #pragma unroll
    for (int j = 0; j < 11; ++j)
        b[j] = (x >= t[j] && x < t[j + 1]) ? 1.0f : 0.0f;

    #pragma unroll
    for (int k = 1; k <= 3; ++k) {
        #pragma unroll
        for (int j = 0; j < 10; ++j) {
            if (j < 11 - k) {
                b[j] = (x - t[j]) / (t[j + k] - t[j]) * b[j]
                     + (t[j + k + 1] - x) / (t[j + k + 1] - t[j + 1]) * b[j + 1];
            }
        }
    }
    #pragma unroll
    for (int s = 0; s < NC; ++s) out[s] = b[s];
}

// ---- Kernel A: fuse base/spline weights into g_fused ----
__global__ void kan_fuse_kernel(const float* __restrict__ base_w,
                                const float* __restrict__ spline_w,
                                const float* __restrict__ spline_s)
{
    const int i = blockIdx.x * blockDim.x + threadIdx.x;
    if (i >= CIN * NF * K2 * COUT) return;
    const int oc  = i & (COUT - 1);
    const int tap = (i / COUT) % K2;
    const int f   = (i / (COUT * K2)) % NF;
    const int c   = i / (COUT * K2 * NF);
    const int widx = (oc * CIN + c) * K2 + tap;
    float w;
    if (f == 0) w = base_w[widx];
    else        w = spline_w[widx * NC + (f - 1)] * spline_s[widx];
    g_fused[i] = w;
}

// ---- Kernel B: main conv.
// Thread layout: tid in [0,256): ocg = tid >> 7 (2 groups of 16 oc),
// pxp = tid & 127 -> vertical pixel pair: r2 = pxp >> 4 (rows 2*r2, 2*r2+1),
// cc = pxp & 15. Whole warp shares one ocg -> weight LDS are broadcasts.
__global__ void __launch_bounds__(THREADS, 2)
kan_conv_kernel(const float* __restrict__ x,
                float* __restrict__ out)
{
    extern __shared__ float smem[];
    float* sF = smem;                 // [NF][18][18]  (current cin)
    float* sW = smem + SF_FLOATS;     // [NF][9][COUT] (current cin)

    const int tid  = threadIdx.x;
    const int tile = blockIdx.x;      // 0..15
    const int b    = blockIdx.y;      // 0..15
    const int th0  = (tile >> 2) * TILE;
    const int tw0  = (tile & 3) * TILE;

    const int ocg = tid >> 7;         // 0..1
    const int pxp = tid & 127;
    const int r2  = pxp >> 4;         // 0..7  -> rows 2*r2, 2*r2+1
    const int cc  = pxp & 15;

    // Accumulators: 2 px x 16 oc = 32 floats as 16 packed f32x2.
    unsigned long long acc0[8], acc1[8];
    #pragma unroll
    for (int q = 0; q < 8; ++q) { acc0[q] = 0ULL; acc1[q] = 0ULL; }

    for (int c = 0; c < CIN; ++c) {
        __syncthreads();   // previous iteration done consuming sF/sW

        // Stage this cin's fused weight chunk (2592 floats) via float4.
        {
            const float4* src =
                reinterpret_cast<const float4*>(g_fused + c * WCHUNK);
            float4* dst = reinterpret_cast<float4*>(sW);
            for (int i = tid; i < WCHUNK / 4; i += THREADS)
                dst[i] = src[i];
        }

        // Feature planes for this cin: sF[f][18][18]
        for (int i = tid; i < FPIX; i += THREADS) {
            const int pc = i % FROWS;
            const int pr = i / FROWS;
            const int gh = th0 + pr - 1;
            const int gw = tw0 + pc - 1;
            float v = 0.0f;
            if (gh >= 0 && gh < HH && gw >= 0 && gw < WW)
                v = x[((b * CIN + c) * HH + gh) * WW + gw];
            float bs[NC];
            bspline8(v, bs);
            sF[i] = silu_f(v);
            #pragma unroll
            for (int s = 0; s < NC; ++s)
                sF[(s + 1) * FPIX + i] = bs[s];
        }
        __syncthreads();

        // Conv-accumulate 9 feature planes of this cin.
        #pragma unroll
        for (int f = 0; f < NF; ++f) {
            // 4 rows x 3 cols feature window for the vertical pixel pair.
            float f12[4][3];
            #pragma unroll
            for (int dh = 0; dh < 4; ++dh)
                #pragma unroll
                for (int dw = 0; dw < 3; ++dw)
                    f12[dh][dw] = sF[f * FPIX + (2 * r2 + dh) * FROWS + (cc + dw)];

            // Weights for (f, ocg): [9 taps][16 oc] -> 4 ulonglong2 per tap.
            const ulonglong2* wv = reinterpret_cast<const ulonglong2*>(
                sW + (f * K2) * COUT + ocg * 16);

            #pragma unroll
            for (int dh = 0; dh < 3; ++dh) {
                #pragma unroll
                for (int dw = 0; dw < 3; ++dw) {
                    const int tap = dh * 3 + dw;
                    const unsigned long long fp0 = pack2(f12[dh][dw]);
                    const unsigned long long fp1 = pack2(f12[dh + 1][dw]);
                    #pragma unroll
                    for (int q = 0; q < 2; ++q) {   // 2 ulonglong2 x 2 = 16 oc
                        const ulonglong2 w =
                            reinterpret_cast<const ulonglong2*>(
                                reinterpret_cast<const char*>(wv) +
                                tap * COUT * 4)[q * 2 + 0];
                        const ulonglong2 w2 =
                            reinterpret_cast<const ulonglong2*>(
                                reinterpret_cast<const char*>(wv) +
                                tap * COUT * 4)[q * 2 + 1];
                        ffma2(acc0[q * 4 + 0], fp0, w.x);
                        ffma2(acc0[q * 4 + 1], fp0, w.y);
                        ffma2(acc0[q * 4 + 2], fp0, w2.x);
                        ffma2(acc0[q * 4 + 3], fp0, w2.y);
                        ffma2(acc1[q * 4 + 0], fp1, w.x);
                        ffma2(acc1[q * 4 + 1], fp1, w.y);
                        ffma2(acc1[q * 4 + 2], fp1, w2.x);
                        ffma2(acc1[q * 4 + 3], fp1, w2.y);
                    }
                }
            }
        }
    }

    // ---- Write out: 2 rows x 16 oc per thread ----
    const int gh0 = th0 + 2 * r2;
    const int gw  = tw0 + cc;
    #pragma unroll
    for (int j = 0; j < 8; ++j) {
        const int oc = ocg * 16 + 2 * j;
        float lo, hi;
        unpack2(acc0[j], lo, hi);
        out[((b * COUT + oc + 0) * HH + gh0) * WW + gw] = lo;
        out[((b * COUT + oc + 1) * HH + gh0) * WW + gw] = hi;
        unpack2(acc1[j], lo, hi);
        out[((b * COUT + oc + 0) * HH + gh0 + 1) * WW + gw] = lo;
        out[((b * COUT + oc + 1) * HH + gh0 + 1) * WW + gw] = hi;
    }
}

extern "C" void kernel_launch(void* const* d_in, const int* in_sizes, int n_in,
                              void* d_out, int out_size) {
    const float* x   = (const float*)d_in[0];
    const float* bw  = (const float*)d_in[1];
    const float* sw  = (const float*)d_in[2];
    const float* ss  = (const float*)d_in[3];
    float* out       = (float*)d_out;

    kan_fuse_kernel<<<(CIN * NF * K2 * COUT + 255) / 256, 256>>>(bw, sw, ss);

    dim3 grid(16, BB);   // 16 spatial tiles x 16 batches
    kan_conv_kernel<<<grid, THREADS, SMEM_BYTES>>>(x, out);
}